// round 7
// baseline (speedup 1.0000x reference)
#include <cuda_runtime.h>
#include <cuda_bf16.h>
#include <cstdint>

#define NB 8
#define TT 20
#define CIN 32
#define COUT 64
#define HH 64
#define WW 64
#define OHH 32
#define OWW 32
#define KTOT (CIN*9)        /* 288 */
#define NCHK 18             /* 288 / 16 */
#define NIMG_SPK (NB*TT)    /* 160 */
#define NIMG (NIMG_SPK+NB)  /* 168 */
#define NNEUR (NB*COUT*OHH*OWW)   /* 524288 */

#define COUNT_OFF (NB*TT*COUT*OHH*OWW)            /* 10485760 */
#define ANN_OFF   (COUNT_OFF + NB*COUT*OHH*OWW)   /* 11010048 */

// -------- device scratch (allocation-free rule) --------
__device__ float g_wT[2][KTOT][COUT];            // folded weights, k-major
__device__ float g_bias[2][COUT];
__device__ uint4 g_bf4[2][NCHK][8][32];          // B frags: splits 0,1
__device__ uint2 g_bf2[2][NCHK][8][32];          // B frags: split 2
__device__ int   g_ktab[KTOT];                   // koff | ky<<24 | kx<<28
__device__ float g_pooled[TT][NB][COUT][OHH*OWW];// 42 MB pre-spike potentials
__device__ int   g_nflag;                        // borderline neuron counter
__device__ int   g_flags[NNEUR];                 // borderline neuron indices

// -------- bf16 split helpers --------
__device__ __forceinline__ unsigned bfbits(float x) {
    __nv_bfloat16 h = __float2bfloat16_rn(x);
    return (unsigned)*reinterpret_cast<unsigned short*>(&h);
}
__device__ __forceinline__ float bfval(unsigned u) {
    return __uint_as_float(u << 16);
}
__device__ __forceinline__ void split3(float x, unsigned& u0, unsigned& u1, unsigned& u2) {
    u0 = bfbits(x);
    float r = x - bfval(u0);
    u1 = bfbits(r);
    float r2 = r - bfval(u1);
    u2 = bfbits(r2);
}

// mma.sync m16n8k16 bf16 (baseline PTX, compiles at compute_100)
#define MMA(C, A, B0, B1) \
    asm volatile("mma.sync.aligned.m16n8k16.row.col.f32.bf16.bf16.f32 " \
                 "{%0,%1,%2,%3},{%4,%5,%6,%7},{%8,%9},{%0,%1,%2,%3};" \
                 : "+f"((C)[0]), "+f"((C)[1]), "+f"((C)[2]), "+f"((C)[3]) \
                 : "r"((A)[0]), "r"((A)[1]), "r"((A)[2]), "r"((A)[3]), \
                   "r"(B0), "r"(B1))

// ---------------------------------------------------------------------------
// prep1: fold BN into weights/bias (set 0: no eps; set 1: eps=1e-5) + ktab.
// Also zeroes the flag counter (runs first on every graph replay).
// ---------------------------------------------------------------------------
__global__ void prep1_kernel(const float* __restrict__ w, const float* __restrict__ b,
                             const float* __restrict__ gamma, const float* __restrict__ beta,
                             const float* __restrict__ rm, const float* __restrict__ rv)
{
    int idx = blockIdx.x * blockDim.x + threadIdx.x;
    if (idx == 0) g_nflag = 0;
    if (idx < 2 * KTOT * COUT) {
        int set = idx / (KTOT * COUT);
        int rem = idx - set * (KTOT * COUT);
        int k  = rem >> 6;
        int co = rem & 63;
        float ratio = gamma[co] / sqrtf(set ? rv[co] + 1e-5f : rv[co]);
        g_wT[set][k][co] = w[co * KTOT + k] * ratio;
    }
    if (idx < 2 * COUT) {
        int set = idx >> 6, co = idx & 63;
        float ratio = gamma[co] / sqrtf(set ? rv[co] + 1e-5f : rv[co]);
        g_bias[set][co] = (b[co] - rm[co]) * ratio + beta[co];
    }
    if (idx < KTOT) {
        int cin = idx / 9, r9 = idx - cin * 9;
        int ky = r9 / 3, kx = r9 - ky * 3;
        g_ktab[idx] = ((cin * HH + ky) * WW + kx) | (ky << 24) | (kx << 28);
    }
}

// ---------------------------------------------------------------------------
// prep2: build B fragments in mma fragment order, 3-way bf16 split.
// ---------------------------------------------------------------------------
__global__ void prep2_kernel()
{
    int idx = blockIdx.x * blockDim.x + threadIdx.x;
    if (idx >= 2 * NCHK * 8 * 32) return;
    int lane = idx & 31;
    int nt   = (idx >> 5) & 7;
    int ch   = (idx >> 8) % NCHK;
    int set  = idx / (NCHK * 8 * 32);

    int t4 = lane & 3, g = lane >> 2;
    int n  = nt * 8 + g;
    int k0 = ch * 16 + 2 * t4;

    float v0 = g_wT[set][k0][n];
    float v1 = g_wT[set][k0 + 1][n];
    float v8 = g_wT[set][k0 + 8][n];
    float v9 = g_wT[set][k0 + 9][n];

    unsigned s0[4], s1[4], s2[4];
    split3(v0, s0[0], s1[0], s2[0]);
    split3(v1, s0[1], s1[1], s2[1]);
    split3(v8, s0[2], s1[2], s2[2]);
    split3(v9, s0[3], s1[3], s2[3]);

    uint4 b4;
    b4.x = s0[0] | (s0[1] << 16);
    b4.y = s0[2] | (s0[3] << 16);
    b4.z = s1[0] | (s1[1] << 16);
    b4.w = s1[2] | (s1[3] << 16);
    uint2 b2;
    b2.x = s2[0] | (s2[1] << 16);
    b2.y = s2[2] | (s2[3] << 16);
    g_bf4[set][ch][nt][lane] = b4;
    g_bf2[set][ch][nt][lane] = b2;
}

// ---------------------------------------------------------------------------
// Conv via mma.sync bf16 (6-term split), fused bias + 2x2 maxpool (+ReLU).
// CTA = (img, pooled row): M=128 pix x N=64 co x K=288. 128 threads, 4 warps.
// ---------------------------------------------------------------------------
__global__ __launch_bounds__(128)
void conv_mma_kernel(const float* __restrict__ x_st, const float* __restrict__ x_sc,
                     float* __restrict__ out)
{
    __shared__ float stg[COUT * 129];
    __shared__ int   skt[KTOT];

    const int img = blockIdx.x;
    const int pr  = blockIdx.y;
    const int tid = threadIdx.x;
    const int wid = tid >> 5;
    const int lane = tid & 31;
    const int g  = lane >> 2;
    const int t4 = lane & 3;
    const int set = (img >= NIMG_SPK) ? 1 : 0;

    const float* inbase = set ? (x_sc + (size_t)(img - NIMG_SPK) * CIN * HH * WW)
                              : (x_st + (size_t)img * CIN * HH * WW);

    for (int i = tid; i < KTOT; i += 128) skt[i] = g_ktab[i];
    __syncthreads();

    float c[2][8][4];
#pragma unroll
    for (int a = 0; a < 2; a++)
#pragma unroll
        for (int b = 0; b < 8; b++)
#pragma unroll
            for (int d = 0; d < 4; d++) c[a][b][d] = 0.f;

#pragma unroll 1
    for (int ch = 0; ch < NCHK; ch++) {
        const int kb = ch * 16 + 2 * t4;
        const int kt[4] = { skt[kb], skt[kb + 1], skt[kb + 8], skt[kb + 9] };

        unsigned afr[2][3][4];
#pragma unroll
        for (int mtl = 0; mtl < 2; mtl++) {
            const int mt = 2 * wid + mtl;
#pragma unroll
            for (int mh = 0; mh < 2; mh++) {
                const int m   = mt * 16 + g + 8 * mh;
                const int row = 2 * pr + (m >> 6);
                const int col = m & 63;
                const int pb  = (row - 1) * WW + (col - 1);
                float v[4];
#pragma unroll
                for (int e = 0; e < 4; e++) {
                    const int kv = kt[e];
                    const int ky = (kv >> 24) & 0xF, kx = (kv >> 28) & 0xF;
                    const int iy = row + ky - 1, ix = col + kx - 1;
                    const bool ok = ((unsigned)iy < HH) & ((unsigned)ix < WW);
                    v[e] = ok ? __ldg(inbase + (kv & 0xFFFFFF) + pb) : 0.f;
                }
                unsigned s[3][4];
#pragma unroll
                for (int e = 0; e < 4; e++) split3(v[e], s[0][e], s[1][e], s[2][e]);
#pragma unroll
                for (int sp = 0; sp < 3; sp++) {
                    afr[mtl][sp][mh]     = s[sp][0] | (s[sp][1] << 16);
                    afr[mtl][sp][mh + 2] = s[sp][2] | (s[sp][3] << 16);
                }
            }
        }

#pragma unroll
        for (int nt = 0; nt < 8; nt++) {
            const uint4 b4 = __ldg(&g_bf4[set][ch][nt][lane]);
            const uint2 b2 = __ldg(&g_bf2[set][ch][nt][lane]);
#pragma unroll
            for (int mtl = 0; mtl < 2; mtl++) {
                float* C = c[mtl][nt];
                MMA(C, afr[mtl][0], b4.x, b4.y);   // a0*b0
                MMA(C, afr[mtl][0], b4.z, b4.w);   // a0*b1
                MMA(C, afr[mtl][1], b4.x, b4.y);   // a1*b0
                MMA(C, afr[mtl][1], b4.z, b4.w);   // a1*b1
                MMA(C, afr[mtl][0], b2.x, b2.y);   // a0*b2
                MMA(C, afr[mtl][2], b4.x, b4.y);   // a2*b0
            }
        }
    }

#pragma unroll
    for (int mtl = 0; mtl < 2; mtl++) {
        const int m0 = (2 * wid + mtl) * 16 + g;
#pragma unroll
        for (int nt = 0; nt < 8; nt++) {
            const int n0 = nt * 8 + 2 * t4;
            stg[n0 * 129 + m0]           = c[mtl][nt][0];
            stg[(n0 + 1) * 129 + m0]     = c[mtl][nt][1];
            stg[n0 * 129 + m0 + 8]       = c[mtl][nt][2];
            stg[(n0 + 1) * 129 + m0 + 8] = c[mtl][nt][3];
        }
    }
    __syncthreads();

    {
        const int tm = tid & 31;
        const int tg = tid >> 5;
        if (!set) {
            int n = img / TT, t = img - n * TT;
            float* dst = &g_pooled[t][n][0][pr * OWW + tm];
#pragma unroll
            for (int j = 0; j < 16; j++) {
                int co = tg * 16 + j;
                const float* r = &stg[co * 129 + 2 * tm];
                float v = fmaxf(fmaxf(r[0], r[1]), fmaxf(r[64], r[65])) + g_bias[0][co];
                dst[(size_t)co * (OHH * OWW)] = v;
            }
        } else {
            int n = img - NIMG_SPK;
            float* dst = out + ANN_OFF + ((size_t)n * COUT * OHH + pr) * OWW + tm;
#pragma unroll
            for (int j = 0; j < 16; j++) {
                int co = tg * 16 + j;
                const float* r = &stg[co * 129 + 2 * tm];
                float v = fmaxf(fmaxf(r[0], r[1]), fmaxf(r[64], r[65])) + g_bias[1][co];
                dst[(size_t)co * (OHH * OWW)] = fmaxf(v, 0.f);
            }
        }
    }
}

// ---------------------------------------------------------------------------
// Temporal LIF scan + borderline flagging. If any pre-spike potential comes
// within 1e-3 of threshold, append neuron to repair list (bf16-path error
// bound << 1e-4, so every possible flip site is captured).
// ---------------------------------------------------------------------------
__global__ void scan_kernel(float* __restrict__ out)
{
    int idx = blockIdx.x * blockDim.x + threadIdx.x;
    if (idx >= NNEUR) return;
    int pix = idx & 1023;
    int c   = (idx >> 10) & 63;
    int n   = idx >> 16;

    const float* src = &g_pooled[0][n][c][pix];
    float* dspike = out + (((size_t)n * TT) * COUT + c) * 1024 + pix;

    float pot = 0.f, mask = 0.f, cnt = 0.f;
    float mindist = 1e30f;
#pragma unroll
    for (int t = 0; t < TT; t++) {
        pot += src[(size_t)t * NB * COUT * 1024];
        mindist = fminf(mindist, fabsf(pot - 1.f));
        float s = (pot >= 1.f) ? (1.f - mask) : 0.f;
        pot -= s;
        if (s != 0.f) mask = 1.f;
        cnt += s;
        dspike[(size_t)t * COUT * 1024] = s;
    }
    out[COUNT_OFF + (size_t)idx] = cnt;

    if (mindist < 1e-3f) {
        int pos = atomicAdd(&g_nflag, 1);
        g_flags[pos] = idx;
    }
}

// ---------------------------------------------------------------------------
// Repair: recompute flagged neurons' full conv+pool+LIF series in fp32
// (same accumulation class as the passing Round-1 scalar kernel).
// Fixed grid, early-exit -> deterministic & graph-capturable.
// ---------------------------------------------------------------------------
__global__ void repair_kernel(const float* __restrict__ x_st, float* __restrict__ out)
{
    int i = blockIdx.x * blockDim.x + threadIdx.x;
    if (i >= g_nflag) return;
    int idx = g_flags[i];
    int pix = idx & 1023;
    int c   = (idx >> 10) & 63;
    int n   = idx >> 16;
    int pr  = pix >> 5, pc = pix & 31;

    const float bias = g_bias[0][c];
    float pot = 0.f, mask = 0.f, cnt = 0.f;
    float* dspike = out + (((size_t)n * TT) * COUT + c) * 1024 + pix;

    for (int t = 0; t < TT; t++) {
        const float* in = x_st + ((size_t)(n * TT + t)) * CIN * HH * WW;
        float m4 = -1e30f;
#pragma unroll
        for (int py = 0; py < 2; py++) {
#pragma unroll
            for (int px = 0; px < 2; px++) {
                int row = 2 * pr + py, col = 2 * pc + px;
                float acc = 0.f;
                for (int cin = 0; cin < CIN; cin++) {
                    const float* ip = in + (size_t)cin * HH * WW;
#pragma unroll
                    for (int ky = 0; ky < 3; ky++) {
#pragma unroll
                        for (int kx = 0; kx < 3; kx++) {
                            int iy = row + ky - 1, ix = col + kx - 1;
                            if ((unsigned)iy < HH && (unsigned)ix < WW)
                                acc = fmaf(__ldg(ip + iy * WW + ix),
                                           g_wT[0][cin * 9 + ky * 3 + kx][c], acc);
                        }
                    }
                }
                m4 = fmaxf(m4, acc);
            }
        }
        pot += m4 + bias;
        float s = (pot >= 1.f) ? (1.f - mask) : 0.f;
        pot -= s;
        if (s != 0.f) mask = 1.f;
        cnt += s;
        dspike[(size_t)t * COUT * 1024] = s;
    }
    out[COUNT_OFF + (size_t)idx] = cnt;
}

// ---------------------------------------------------------------------------
extern "C" void kernel_launch(void* const* d_in, const int* in_sizes, int n_in,
                              void* d_out, int out_size)
{
    const float* x_st  = (const float*)d_in[0];
    const float* x_sc  = (const float*)d_in[1];
    const float* w     = (const float*)d_in[2];
    const float* b     = (const float*)d_in[3];
    const float* gamma = (const float*)d_in[4];
    const float* beta  = (const float*)d_in[5];
    const float* rm    = (const float*)d_in[6];
    const float* rv    = (const float*)d_in[7];
    float* out = (float*)d_out;
    (void)in_sizes; (void)n_in; (void)out_size;

    prep1_kernel<<<(2 * KTOT * COUT + 255) / 256, 256>>>(w, b, gamma, beta, rm, rv);
    prep2_kernel<<<(2 * NCHK * 8 * 32 + 255) / 256, 256>>>();
    conv_mma_kernel<<<dim3(NIMG, OHH), 128>>>(x_st, x_sc, out);
    scan_kernel<<<(NNEUR + 255) / 256, 256>>>(out);
    repair_kernel<<<(NNEUR + 127) / 128, 128>>>(x_st, out);
}

// round 8
// speedup vs baseline: 7.4890x; 7.4890x over previous
#include <cuda_runtime.h>
#include <cstdint>

#define NB 8
#define TT 20
#define CIN 32
#define COUT 64
#define HH 64
#define WW 64
#define OHH 32
#define OWW 32
#define KTOT 288
#define NIMG_SPK 160
#define NIMG 168
#define NNEUR (NB*COUT*OHH*OWW)                   /* 524288 */
#define COUNT_OFF (NB*TT*COUT*OHH*OWW)            /* 10485760 */
#define ANN_OFF (COUNT_OFF + NB*COUT*OHH*OWW)     /* 11010048 */

// -------- device scratch (allocation-free rule) --------
__device__ float g_wT[2][KTOT][COUT];             // folded weights, k-major
__device__ float g_bias[2][COUT];
__device__ float g_Wf[2][16][CIN*COUT];           // winograd weights [set][f][cin*64+co]
__device__ float g_pooled[TT][NB][COUT][OHH*OWW]; // 42 MB pre-spike potentials
__device__ int   g_nflag;
__device__ int   g_flags[NNEUR];

// Winograd F(2,3) constant tables.
// B^T rows: nonzero cols + signs;  A^T rows (output transform coeffs).
__constant__ int   c_bi[4][2] = {{0,2},{1,2},{1,2},{1,3}};
__constant__ float c_bs[4][2] = {{1.f,-1.f},{1.f,1.f},{-1.f,1.f},{1.f,-1.f}};
__constant__ float c_at[2][4] = {{1.f,1.f,1.f,0.f},{0.f,1.f,-1.f,-1.f}};

typedef unsigned long long u64;
__device__ __forceinline__ void fma2(u64& d, u64 a, u64 b) {
    asm("fma.rn.f32x2 %0, %1, %2, %0;" : "+l"(d) : "l"(a), "l"(b));
}
__device__ __forceinline__ u64 dup2(float x) {
    u64 d; unsigned u = __float_as_uint(x);
    asm("mov.b64 %0, {%1, %1};" : "=l"(d) : "r"(u));
    return d;
}
__device__ __forceinline__ void unpack2(u64 v, float& lo, float& hi) {
    unsigned a, b;
    asm("mov.b64 {%0, %1}, %2;" : "=r"(a), "=r"(b) : "l"(v));
    lo = __uint_as_float(a); hi = __uint_as_float(b);
}

// ---------------------------------------------------------------------------
// prep1: fold BN into weights/bias. set 0: ratio = gamma/sqrt(rv) (NO eps,
// spiking path); set 1: gamma/sqrt(rv+1e-5) (ANN path). Zeroes flag counter.
// ---------------------------------------------------------------------------
__global__ void prep1_kernel(const float* __restrict__ w, const float* __restrict__ b,
                             const float* __restrict__ gamma, const float* __restrict__ beta,
                             const float* __restrict__ rm, const float* __restrict__ rv)
{
    int idx = blockIdx.x * blockDim.x + threadIdx.x;
    if (idx == 0) g_nflag = 0;
    if (idx < 2 * KTOT * COUT) {
        int set = idx / (KTOT * COUT);
        int rem = idx - set * (KTOT * COUT);
        int k  = rem >> 6;
        int co = rem & 63;
        float ratio = gamma[co] / sqrtf(set ? rv[co] + 1e-5f : rv[co]);
        g_wT[set][k][co] = w[co * KTOT + k] * ratio;
    }
    if (idx < 2 * COUT) {
        int set = idx >> 6, co = idx & 63;
        float ratio = gamma[co] / sqrtf(set ? rv[co] + 1e-5f : rv[co]);
        g_bias[set][co] = (b[co] - rm[co]) * ratio + beta[co];
    }
}

// ---------------------------------------------------------------------------
// prep2: Winograd weight transform U = G w G^T per (set, cin, cout).
// ---------------------------------------------------------------------------
__global__ void prep2_kernel()
{
    int idx = blockIdx.x * blockDim.x + threadIdx.x;
    if (idx >= 2 * CIN * COUT) return;
    int set = idx / (CIN * COUT);
    int rem = idx - set * (CIN * COUT);
    int cin = rem >> 6, co = rem & 63;

    float w[3][3];
#pragma unroll
    for (int ky = 0; ky < 3; ky++)
#pragma unroll
        for (int kx = 0; kx < 3; kx++)
            w[ky][kx] = g_wT[set][cin * 9 + ky * 3 + kx][co];

    float t[4][3];
#pragma unroll
    for (int j = 0; j < 3; j++) {
        t[0][j] = w[0][j];
        t[1][j] = 0.5f * (w[0][j] + w[1][j] + w[2][j]);
        t[2][j] = 0.5f * (w[0][j] - w[1][j] + w[2][j]);
        t[3][j] = w[2][j];
    }
    float U[4][4];
#pragma unroll
    for (int i = 0; i < 4; i++) {
        U[i][0] = t[i][0];
        U[i][1] = 0.5f * (t[i][0] + t[i][1] + t[i][2]);
        U[i][2] = 0.5f * (t[i][0] - t[i][1] + t[i][2]);
        U[i][3] = t[i][2];
    }
#pragma unroll
    for (int f = 0; f < 16; f++)
        g_Wf[set][f][cin * 64 + co] = U[f >> 2][f & 3];
}

// ---------------------------------------------------------------------------
// Winograd conv + bias + pool (+ReLU for ANN). CTA = (img, pooled-row-pair).
// 64 tiles (2x2 out each == one pool window), 32 cin, 64 cout.
// smem: raw input [32][6][66] + V_f [32][64] + W_f [32][64].
// Per freq: transform V -> K=32 GEMM (f32x2 FMAs) -> A^T scatter into out accs.
// ---------------------------------------------------------------------------
#define S_IN (CIN*6*66)                /* 12672 floats */
#define OFF_V S_IN
#define OFF_W (S_IN + CIN*64)
#define SM_BYTES ((S_IN + 2*CIN*64) * 4)   /* 67072 */

__global__ __launch_bounds__(256, 2)
void conv_wino_kernel(const float* __restrict__ x_st, const float* __restrict__ x_sc,
                      float* __restrict__ out)
{
    extern __shared__ float sm[];
    float* sIn = sm;
    float* sV  = sm + OFF_V;
    float* sW  = sm + OFF_W;

    const int img = blockIdx.x;
    const int prr = blockIdx.y;          // pooled row pair 0..15
    const int tid = threadIdx.x;
    const int lane = tid & 31;           // tile pair index
    const int cg   = tid >> 5;           // cout group (8 couts)
    const int set = (img >= NIMG_SPK) ? 1 : 0;

    const float* inbase = set ? (x_sc + (size_t)(img - NIMG_SPK) * CIN * HH * WW)
                              : (x_st + (size_t)img * CIN * HH * WW);

    // ---- load input slab: rows 4prr-1 .. 4prr+4, cols -1..64, zero-padded ----
    const int r0 = 4 * prr - 1;
    for (int i = tid; i < S_IN; i += 256) {
        int cin = i / 396;
        int rem = i - cin * 396;
        int r = rem / 66, cc = rem - r * 66;
        int gr = r0 + r, gc = cc - 1;
        float v = 0.f;
        if ((unsigned)gr < HH && (unsigned)gc < WW)
            v = inbase[cin * (HH * WW) + gr * WW + gc];
        sIn[i] = v;
    }

    u64 acc[2][4][4];                    // [tile][co-pair][2y+x]
#pragma unroll
    for (int t = 0; t < 2; t++)
#pragma unroll
        for (int q = 0; q < 4; q++)
#pragma unroll
            for (int p = 0; p < 4; p++) acc[t][q][p] = 0ull;

#pragma unroll 1
    for (int f = 0; f < 16; f++) {
        const int fy = f >> 2, fx = f & 3;
        const int i1 = c_bi[fy][0], i2 = c_bi[fy][1];
        const int j1 = c_bi[fx][0], j2 = c_bi[fx][1];
        const float sy1 = c_bs[fy][0], sy2 = c_bs[fy][1];
        const float sx1 = c_bs[fx][0], sx2 = c_bs[fx][1];

        __syncthreads();                 // previous GEMM done / sIn ready (f==0)

        // V transform: 2048 elements = 8 per thread
#pragma unroll
        for (int k = 0; k < 8; k++) {
            int el = tid + 256 * k;
            int cin = el >> 6, t = el & 63;
            int ty = t >> 5, tx = t & 31;
            const float* p = &sIn[cin * 396 + (2 * ty) * 66 + 2 * tx];
            float a = sx1 * p[i1 * 66 + j1] + sx2 * p[i1 * 66 + j2];
            float b = sx1 * p[i2 * 66 + j1] + sx2 * p[i2 * 66 + j2];
            sV[cin * 64 + t] = sy1 * a + sy2 * b;
        }
        // W copy (2048 floats, 2x float4 per thread; L2-resident across CTAs)
        {
            const float4* gw = (const float4*)g_Wf[set][f];
            ((float4*)sW)[tid]       = gw[tid];
            ((float4*)sW)[tid + 256] = gw[tid + 256];
        }
        __syncthreads();

        // GEMM: M_f[2 tiles][8 couts] over K=32
        u64 M[8];
#pragma unroll
        for (int q = 0; q < 8; q++) M[q] = 0ull;
#pragma unroll 8
        for (int cin = 0; cin < CIN; cin++) {
            float2 v = *(const float2*)&sV[cin * 64 + 2 * lane];
            ulonglong2 w0 = *(const ulonglong2*)&sW[cin * 64 + 8 * cg];
            ulonglong2 w1 = *(const ulonglong2*)&sW[cin * 64 + 8 * cg + 4];
            u64 vx = dup2(v.x), vy = dup2(v.y);
            fma2(M[0], vx, w0.x); fma2(M[1], vx, w0.y);
            fma2(M[2], vx, w1.x); fma2(M[3], vx, w1.y);
            fma2(M[4], vy, w0.x); fma2(M[5], vy, w0.y);
            fma2(M[6], vy, w1.x); fma2(M[7], vy, w1.y);
        }

        // A^T scatter: out[y][x] += AT[y][fy]*AT[x][fx] * M   (coeffs 0/±1)
#pragma unroll
        for (int y = 0; y < 2; y++) {
            float cy = c_at[y][fy];
            if (cy == 0.f) continue;
#pragma unroll
            for (int x = 0; x < 2; x++) {
                float cx = c_at[x][fx];
                if (cx == 0.f) continue;
                u64 cd = dup2(cy * cx);
#pragma unroll
                for (int t = 0; t < 2; t++)
#pragma unroll
                    for (int q = 0; q < 4; q++)
                        fma2(acc[t][q][2 * y + x], cd, M[4 * t + q]);
            }
        }
    }

    // ---- epilogue: max over 2x2 (== pool window) + bias (+ReLU), store ----
#pragma unroll
    for (int t = 0; t < 2; t++) {
        int tix = 2 * lane + t;
        int prow = 2 * prr + (tix >> 5);
        int tx = tix & 31;
#pragma unroll
        for (int q = 0; q < 4; q++) {
            int co = 8 * cg + 2 * q;
            float l0, h0, l1, h1, l2, h2, l3, h3;
            unpack2(acc[t][q][0], l0, h0);
            unpack2(acc[t][q][1], l1, h1);
            unpack2(acc[t][q][2], l2, h2);
            unpack2(acc[t][q][3], l3, h3);
            float vlo = fmaxf(fmaxf(l0, l1), fmaxf(l2, l3)) + g_bias[set][co];
            float vhi = fmaxf(fmaxf(h0, h1), fmaxf(h2, h3)) + g_bias[set][co + 1];
            if (!set) {
                int n = img / TT, tt = img - n * TT;
                float* dst = &g_pooled[tt][n][co][prow * OWW + tx];
                dst[0] = vlo;
                dst[OHH * OWW] = vhi;
            } else {
                int n = img - NIMG_SPK;
                float* dst = out + ANN_OFF + ((size_t)(n * COUT + co) * OHH + prow) * OWW + tx;
                dst[0] = fmaxf(vlo, 0.f);
                dst[OHH * OWW] = fmaxf(vhi, 0.f);
            }
        }
    }
}

// ---------------------------------------------------------------------------
// LIF scan + borderline flagging (δ=2e-4 >> Winograd pot-error bound ~5e-5).
// ---------------------------------------------------------------------------
__global__ void scan_kernel(float* __restrict__ out)
{
    int idx = blockIdx.x * blockDim.x + threadIdx.x;
    if (idx >= NNEUR) return;
    int pix = idx & 1023;
    int c   = (idx >> 10) & 63;
    int n   = idx >> 16;

    const float* src = &g_pooled[0][n][c][pix];
    float* dspike = out + (((size_t)n * TT) * COUT + c) * 1024 + pix;

    float pot = 0.f, mask = 0.f, cnt = 0.f;
    float mindist = 1e30f;
#pragma unroll
    for (int t = 0; t < TT; t++) {
        pot += src[(size_t)t * NB * COUT * 1024];
        mindist = fminf(mindist, fabsf(pot - 1.f));
        float s = (pot >= 1.f) ? (1.f - mask) : 0.f;
        pot -= s;
        if (s != 0.f) mask = 1.f;
        cnt += s;
        dspike[(size_t)t * COUT * 1024] = s;
    }
    out[COUNT_OFF + (size_t)idx] = cnt;

    if (mindist < 2e-4f) {
        int pos = atomicAdd(&g_nflag, 1);
        g_flags[pos] = idx;
    }
}

// ---------------------------------------------------------------------------
// Repair: warp-per-neuron fp32 direct recompute (lane = cin, 9 taps/lane,
// butterfly reduce). Fixed grid + stride loop over g_nflag: deterministic,
// graph-capturable, order-independent (disjoint writes).
// ---------------------------------------------------------------------------
__global__ void repair_kernel(const float* __restrict__ x_st, float* __restrict__ out)
{
    const int gw = (blockIdx.x * blockDim.x + threadIdx.x) >> 5;
    const int lane = threadIdx.x & 31;
    const int nwarps = (gridDim.x * blockDim.x) >> 5;
    const int nf = g_nflag;

    for (int i = gw; i < nf; i += nwarps) {
        int idx = g_flags[i];
        int pix = idx & 1023;
        int c   = (idx >> 10) & 63;
        int n   = idx >> 16;
        int pr  = pix >> 5, pc = pix & 31;

        const float bias = g_bias[0][c];
        float wv[9];
#pragma unroll
        for (int k = 0; k < 9; k++) wv[k] = g_wT[0][lane * 9 + k][c];

        float pot = 0.f, mask = 0.f, cnt = 0.f;
        float* dspike = out + (((size_t)n * TT) * COUT + c) * 1024 + pix;

        for (int t = 0; t < TT; t++) {
            const float* in = x_st + ((size_t)(n * TT + t)) * CIN * HH * WW
                                   + (size_t)lane * HH * WW;
            float m4 = -1e30f;
#pragma unroll
            for (int py = 0; py < 2; py++) {
#pragma unroll
                for (int px = 0; px < 2; px++) {
                    int row = 2 * pr + py, col = 2 * pc + px;
                    float acc = 0.f;
#pragma unroll
                    for (int ky = 0; ky < 3; ky++) {
#pragma unroll
                        for (int kx = 0; kx < 3; kx++) {
                            int iy = row + ky - 1, ix = col + kx - 1;
                            if ((unsigned)iy < HH && (unsigned)ix < WW)
                                acc = fmaf(__ldg(in + iy * WW + ix), wv[ky * 3 + kx], acc);
                        }
                    }
#pragma unroll
                    for (int off = 16; off > 0; off >>= 1)
                        acc += __shfl_xor_sync(0xFFFFFFFF, acc, off);
                    m4 = fmaxf(m4, acc);
                }
            }
            pot += m4 + bias;
            float s = (pot >= 1.f) ? (1.f - mask) : 0.f;
            pot -= s;
            if (s != 0.f) mask = 1.f;
            cnt += s;
            if (lane == 0) dspike[(size_t)t * COUT * 1024] = s;
        }
        if (lane == 0) out[COUNT_OFF + (size_t)idx] = cnt;
    }
}

// ---------------------------------------------------------------------------
extern "C" void kernel_launch(void* const* d_in, const int* in_sizes, int n_in,
                              void* d_out, int out_size)
{
    const float* x_st  = (const float*)d_in[0];
    const float* x_sc  = (const float*)d_in[1];
    const float* w     = (const float*)d_in[2];
    const float* b     = (const float*)d_in[3];
    const float* gamma = (const float*)d_in[4];
    const float* beta  = (const float*)d_in[5];
    const float* rm    = (const float*)d_in[6];
    const float* rv    = (const float*)d_in[7];
    float* out = (float*)d_out;
    (void)in_sizes; (void)n_in; (void)out_size;

    cudaFuncSetAttribute(conv_wino_kernel,
                         cudaFuncAttributeMaxDynamicSharedMemorySize, SM_BYTES);

    prep1_kernel<<<(2 * KTOT * COUT + 255) / 256, 256>>>(w, b, gamma, beta, rm, rv);
    prep2_kernel<<<(2 * CIN * COUT + 255) / 256, 256>>>();
    conv_wino_kernel<<<dim3(NIMG, 16), 256, SM_BYTES>>>(x_st, x_sc, out);
    scan_kernel<<<(NNEUR + 255) / 256, 256>>>(out);
    repair_kernel<<<256, 128>>>(x_st, out);
}